// round 8
// baseline (speedup 1.0000x reference)
#include <cuda_runtime.h>
#include <cuda_fp16.h>
#include <math.h>
#include <math_constants.h>

// EM routing, matrix capsules.
// N=4, child 12x12, kernel 3, stride 1 -> P=10, tiles = 4*100 = 400
// K=144 (9 slots x 16 child caps), O=32 parent caps, ch=16 pose dims.
// votes: (400, 144, 32, 16) f32 ; acts: (400, 144) ; beta_v/beta_a: (32)
// Output: poses (400*32*16 = 204800 floats) then activations (400*32).
//
// fp16 votes cache (59 MB, L2-resident after mz0) + e-step fused into the
// consumer mz kernel. g_z is DOUBLE-BUFFERED: each launch reads buffer RD
// and writes buffer RD^1, so the fused neighbor-z gather can never race
// with the same launch's pass-2 z writes (the R6 bug).

#define NTILES 400
#define KTOT   144
#define OCAPS  32
#define CH     16
#define TILE_ELEMS (KTOT*OCAPS*CH)   // 73728
#define ZPT    (KTOT*OCAPS)          // 4608
#define EPS    1e-9f
#define LNF    22.2222222222222222f  // 100/(144/32)
#define TWO_PI 6.2831853071795864f
#define NCELLS 144                   // 12*12 child cells

__device__ float g_z [2][NTILES*ZPT];                 // double-buffered (tile, k, o)
__device__ uint4 g_vh[(size_t)NTILES*TILE_ELEMS/8];   // fp16 votes cache (59 MB)

__device__ __forceinline__ float sigmoidf_(float x) { return 1.0f/(1.0f+__expf(-x)); }

template<bool INIT_RR, bool FINAL, int RD>
__global__ void __launch_bounds__(512)
mz_kernel(const float* __restrict__ votes, const float* __restrict__ acti,
          const float* __restrict__ beta_v, const float* __restrict__ beta_a,
          float lam, float* __restrict__ out)
{
    const int tile = blockIdx.x;
    const int n = tile / 100, p = tile % 100;
    const int pr = p / 10, pc = p % 10;
    const float* V = votes + (size_t)tile * TILE_ELEMS;
    __half* VH = ((__half*)g_vh) + (size_t)tile * TILE_ELEMS;

    __shared__ float w_s[ZPT];           // rr*act  [k][o]
    __shared__ float acti_s[KTOT];
    __shared__ float m_s[KTOT];          // softmax max per k (slot,cc)
    __shared__ float dinv_s[KTOT];
    __shared__ float ps1[4*512];         // pass1 partials [part][o*16+c]
    __shared__ float ps2[4*512];
    __shared__ float rp[16*OCAPS];       // rrs partials
    __shared__ float rrs_s[OCAPS];
    __shared__ float mean_cs[CH*OCAPS];  // [c][o]
    __shared__ float i2v_cs[CH*OCAPS];   // 1/(2 var) [c][o]
    __shared__ float cost_s[OCAPS];
    __shared__ float logact_s[OCAPS];
    __shared__ float op2_s[OCAPS];

    const int t = threadIdx.x;
    if (t < KTOT) acti_s[t] = acti[tile*KTOT + t];

    // ---- fused e-step: softmax stats m/dinv for this tile's 144 k's ----
    // Reads z from buffer RD (written by the PREVIOUS launch; this launch
    // writes only buffer RD^1, so no intra-launch race).
    // Load order + shuffle reductions bitwise-identical to R4's estep.
    if (!INIT_RR) {
        const float* Zr = g_z[RD];
        const int wi = t >> 5, o = t & 31;
        #pragma unroll
        for (int j = 0; j < 9; j++) {
            const int k = wi*9 + j;
            const int slot = k >> 4, ccp = k & 15;
            const int r = pr + slot/3, ccol = pc + slot%3;   // child cell
            float zb[9];
            float m = -CUDART_INF_F;
            #pragma unroll
            for (int dr = 0; dr < 3; dr++) {
                #pragma unroll
                for (int dc = 0; dc < 3; dc++) {
                    const int i = dr*3 + dc;
                    const int pr2 = r - dr, pc2 = ccol - dc;
                    if (pr2 >= 0 && pr2 < 10 && pc2 >= 0 && pc2 < 10) {
                        const int p2 = pr2*10 + pc2;
                        zb[i] = Zr[((size_t)(n*100 + p2))*ZPT + (i*CH + ccp)*OCAPS + o];
                        m = fmaxf(m, zb[i]);
                    } else {
                        zb[i] = -CUDART_INF_F;
                    }
                }
            }
            #pragma unroll
            for (int off = 16; off > 0; off >>= 1)
                m = fmaxf(m, __shfl_xor_sync(0xffffffffu, m, off));
            if (isinf(m)) m = 0.0f;

            float s = 0.f;
            #pragma unroll
            for (int i = 0; i < 9; i++)
                s += __expf(zb[i] - m);
            #pragma unroll
            for (int off = 16; off > 0; off >>= 1)
                s += __shfl_xor_sync(0xffffffffu, s, off);

            if (o == 0) { m_s[k] = m; dinv_s[k] = 1.0f / s; }
        }
    }
    __syncthreads();

    // ---- build w = rr * act_i ----
    if (INIT_RR) {
        for (int idx = t; idx < ZPT; idx += 512) {
            int k = idx >> 5;
            int slot = k >> 4;
            int r = pr + slot/3, c = pc + slot%3;
            int cr = min(r,9) - max(0,r-2) + 1;
            int cc = min(c,9) - max(0,c-2) + 1;
            float rrv = 1.0f / ((float)(cr*cc) * (float)OCAPS + EPS);
            w_s[idx] = rrv * acti_s[k];
        }
    } else {
        const float* Zown = g_z[RD] + (size_t)tile * ZPT;
        for (int idx = t; idx < ZPT; idx += 512) {
            int k = idx >> 5;
            w_s[idx] = __expf(Zown[idx] - m_s[k]) * dinv_s[k] * acti_s[k];
        }
    }
    __syncthreads();

    // ---- rrs: sum_k w[k][o], parallel ----
    {
        const int o = t & 31, seg = t >> 5;        // 16 segs x 9 k
        float sp = 0.f;
        #pragma unroll
        for (int j = 0; j < 9; j++) sp += w_s[(seg*9 + j)*OCAPS + o];
        rp[seg*OCAPS + o] = sp;
    }
    __syncthreads();
    if (t < OCAPS) {
        float s = 0.f;
        #pragma unroll
        for (int i = 0; i < 16; i++) s += rp[i*OCAPS + t];
        rrs_s[t] = s;
    }

    // ---- pass 1: weighted sums over K (k-split x vectorized) ----
    {
        const int cq = t & 3, o1 = (t >> 2) & 31, part = t >> 7;
        float4 s1 = make_float4(0.f,0.f,0.f,0.f);
        float4 s2 = make_float4(0.f,0.f,0.f,0.f);
        const int kbeg = part * 36;
        if (INIT_RR) {
            const float4* V4 = (const float4*)V;
            #pragma unroll 4
            for (int kk2 = 0; kk2 < 36; kk2++) {
                const int k = kbeg + kk2;
                float4 v = V4[k*128 + o1*4 + cq];
                float w = w_s[k*OCAPS + o1];
                s1.x = fmaf(w, v.x, s1.x); s2.x = fmaf(w*v.x, v.x, s2.x);
                s1.y = fmaf(w, v.y, s1.y); s2.y = fmaf(w*v.y, v.y, s2.y);
                s1.z = fmaf(w, v.z, s1.z); s2.z = fmaf(w*v.z, v.z, s2.z);
                s1.w = fmaf(w, v.w, s1.w); s2.w = fmaf(w*v.w, v.w, s2.w);
                union { __half2 h[2]; uint2 u; } cv;
                cv.h[0] = __floats2half2_rn(v.x, v.y);
                cv.h[1] = __floats2half2_rn(v.z, v.w);
                *(uint2*)(VH + k*512 + o1*16 + cq*4) = cv.u;
            }
        } else {
            #pragma unroll 4
            for (int kk2 = 0; kk2 < 36; kk2++) {
                const int k = kbeg + kk2;
                union { uint2 u; __half2 h[2]; } cv;
                cv.u = *(const uint2*)(VH + k*512 + o1*16 + cq*4);
                float2 f01 = __half22float2(cv.h[0]);
                float2 f23 = __half22float2(cv.h[1]);
                float w = w_s[k*OCAPS + o1];
                s1.x = fmaf(w, f01.x, s1.x); s2.x = fmaf(w*f01.x, f01.x, s2.x);
                s1.y = fmaf(w, f01.y, s1.y); s2.y = fmaf(w*f01.y, f01.y, s2.y);
                s1.z = fmaf(w, f23.x, s1.z); s2.z = fmaf(w*f23.x, f23.x, s2.z);
                s1.w = fmaf(w, f23.y, s1.w); s2.w = fmaf(w*f23.y, f23.y, s2.w);
            }
        }
        ((float4*)(ps1 + part*512))[o1*4 + cq] = s1;
        ((float4*)(ps2 + part*512))[o1*4 + cq] = s2;
    }
    __syncthreads();

    // ---- per-(o,c) stats; thread t = o*16 + c ----
    const int o = t >> 4, c = t & 15;
    const float S1 = ps1[t] + ps1[512+t] + ps1[1024+t] + ps1[1536+t];
    const float S2 = ps2[t] + ps2[512+t] + ps2[1024+t] + ps2[1536+t];

    const float rrs = rrs_s[o];
    const float inv = 1.0f / (rrs + EPS);
    const float mean = S1 * inv;
    const float var = (S2 - 2.f*mean*S1 + mean*mean*rrs) * inv;  // exact expansion

    float cj = (beta_v[o] + 0.5f*logf(var + EPS)) * rrs * LNF;
    #pragma unroll
    for (int off = 8; off > 0; off >>= 1)
        cj += __shfl_xor_sync(0xffffffffu, cj, off, 16);

    if (!FINAL) {
        float op2 = -0.5f * logf(TWO_PI * var);
        #pragma unroll
        for (int off = 8; off > 0; off >>= 1)
            op2 += __shfl_xor_sync(0xffffffffu, op2, off, 16);
        if (c == 0) op2_s[o] = op2;
        mean_cs[c*OCAPS + o] = mean;
        i2v_cs[c*OCAPS + o]  = 0.5f / var;
    }
    if (c == 0) cost_s[o] = cj;
    __syncthreads();

    if (t < OCAPS) {
        float cost = cost_s[t];
        float cm = cost;
        #pragma unroll
        for (int off = 16; off > 0; off >>= 1)
            cm += __shfl_xor_sync(0xffffffffu, cm, off);
        cm *= (1.0f/32.0f);
        float d = cost - cm;
        float ss = d*d;
        #pragma unroll
        for (int off = 16; off > 0; off >>= 1)
            ss += __shfl_xor_sync(0xffffffffu, ss, off);
        float stdv = sqrtf(ss * (1.0f/32.0f));
        float a = sigmoidf_(lam * (beta_a[t] + (cm - cost)/(stdv + EPS)));
        if (FINAL) out[204800 + tile*OCAPS + t] = a;
        else       logact_s[t] = logf(a + EPS);
    }

    if (FINAL) {
        out[(size_t)tile*512 + t] = mean;   // poses (tile, o, c)
        return;
    }
    __syncthreads();

    // ---- pass 2: z[k][o] -> buffer RD^1 ----
    float* Z = g_z[RD ^ 1] + (size_t)tile * ZPT;
    const int o2 = t & 31, k0 = t >> 5;        // warp = one k0, lanes = o
    const float zc = logact_s[o2] + op2_s[o2];
    #pragma unroll
    for (int j = 0; j < 9; j++) {
        int k = k0*9 + j;
        const uint4* vp = (const uint4*)(VH + k*512 + o2*CH);
        float s = 0.f;
        #pragma unroll
        for (int h8 = 0; h8 < 2; h8++) {
            union { uint4 u; __half2 h[4]; } cv;
            cv.u = vp[h8];
            #pragma unroll
            for (int q = 0; q < 4; q++) {
                float2 f = __half22float2(cv.h[q]);
                int cb = h8*8 + q*2;
                float d;
                d = f.x - mean_cs[(cb+0)*OCAPS + o2]; s = fmaf(d*d, i2v_cs[(cb+0)*OCAPS + o2], s);
                d = f.y - mean_cs[(cb+1)*OCAPS + o2]; s = fmaf(d*d, i2v_cs[(cb+1)*OCAPS + o2], s);
            }
        }
        Z[k*OCAPS + o2] = zc - s;
    }
}

extern "C" void kernel_launch(void* const* d_in, const int* in_sizes, int n_in,
                              void* d_out, int out_size)
{
    const float* votes  = (const float*)d_in[0];
    const float* acti   = (const float*)d_in[1];
    const float* beta_v = (const float*)d_in[2];
    const float* beta_a = (const float*)d_in[3];
    float* out = (float*)d_out;

    const float lam0 = 0.01f * (1.0f - 0.95f);
    const float lam1 = 0.01f * (1.0f - 0.95f*0.95f);
    const float lam2 = 0.01f * (1.0f - 0.95f*0.95f*0.95f);

    // mz0 writes z -> buf 1 ; mz1 reads buf 1, writes buf 0 ; mz2 reads buf 0.
    mz_kernel<true,  false, 0><<<NTILES, 512>>>(votes, acti, beta_v, beta_a, lam0, nullptr);
    mz_kernel<false, false, 1><<<NTILES, 512>>>(votes, acti, beta_v, beta_a, lam1, nullptr);
    mz_kernel<false, true,  0><<<NTILES, 512>>>(votes, acti, beta_v, beta_a, lam2, out);
}

// round 9
// speedup vs baseline: 1.1930x; 1.1930x over previous
#include <cuda_runtime.h>
#include <cuda_fp16.h>
#include <math.h>
#include <math_constants.h>

// EM routing, matrix capsules.
// N=4, child 12x12, kernel 3, stride 1 -> P=10, tiles = 4*100 = 400
// K=144 (9 slots x 16 child caps), O=32 parent caps, ch=16 pose dims.
// votes: (400, 144, 32, 16) f32 ; acts: (400, 144) ; beta_v/beta_a: (32)
// Output: poses (400*32*16 = 204800 floats) then activations (400*32).
//
// R4 split structure (fastest known): fp16 votes cache (59 MB, L2-resident
// after mz0), standalone estep kernel between mz launches.
// R9: __launch_bounds__(512,3) on mz -> 3 CTAs/SM (was register-limited to 2).

#define NTILES 400
#define KTOT   144
#define OCAPS  32
#define CH     16
#define TILE_ELEMS (KTOT*OCAPS*CH)   // 73728
#define ZPT    (KTOT*OCAPS)          // 4608
#define EPS    1e-9f
#define LNF    22.2222222222222222f  // 100/(144/32)
#define TWO_PI 6.2831853071795864f
#define NCELLS 144                   // 12*12 child cells

__device__ float g_z   [NTILES*ZPT];              // (tile, k, o)
__device__ float g_m   [4*NCELLS*CH];             // softmax max per (n, cell, cc)
__device__ float g_dinv[4*NCELLS*CH];             // 1/denom per (n, cell, cc)
__device__ uint4 g_vh  [(size_t)NTILES*TILE_ELEMS/8];  // fp16 votes cache (59 MB)

__device__ __forceinline__ float sigmoidf_(float x) { return 1.0f/(1.0f+__expf(-x)); }

template<bool INIT_RR, bool FINAL>
__global__ void __launch_bounds__(512, 3)
mz_kernel(const float* __restrict__ votes, const float* __restrict__ acti,
          const float* __restrict__ beta_v, const float* __restrict__ beta_a,
          float lam, float* __restrict__ out)
{
    const int tile = blockIdx.x;
    const int n = tile / 100, p = tile % 100;
    const int pr = p / 10, pc = p % 10;
    const float* V = votes + (size_t)tile * TILE_ELEMS;
    __half* VH = ((__half*)g_vh) + (size_t)tile * TILE_ELEMS;

    __shared__ float w_s[ZPT];           // rr*act  [k][o]
    __shared__ float acti_s[KTOT];
    __shared__ float m_s[KTOT];          // softmax max per k (slot,cc)
    __shared__ float dinv_s[KTOT];
    __shared__ float ps1[4*512];         // pass1 partials [part][o*16+c]
    __shared__ float ps2[4*512];
    __shared__ float rp[16*OCAPS];       // rrs partials
    __shared__ float rrs_s[OCAPS];
    __shared__ float mean_cs[CH*OCAPS];  // [c][o]
    __shared__ float i2v_cs[CH*OCAPS];   // 1/(2 var) [c][o]
    __shared__ float cost_s[OCAPS];
    __shared__ float logact_s[OCAPS];
    __shared__ float op2_s[OCAPS];

    const int t = threadIdx.x;
    if (t < KTOT) {
        acti_s[t] = acti[tile*KTOT + t];
        if (!INIT_RR) {
            const int slot = t >> 4, ccp = t & 15;
            const int r = pr + slot/3, ccol = pc + slot%3;
            const int gi = ((n*NCELLS) + r*12 + ccol)*CH + ccp;
            m_s[t]    = g_m[gi];
            dinv_s[t] = g_dinv[gi];
        }
    }
    __syncthreads();

    // ---- build w = rr * act_i ----
    if (INIT_RR) {
        for (int idx = t; idx < ZPT; idx += 512) {
            int k = idx >> 5;
            int slot = k >> 4;
            int r = pr + slot/3, c = pc + slot%3;
            int cr = min(r,9) - max(0,r-2) + 1;
            int cc = min(c,9) - max(0,c-2) + 1;
            float rrv = 1.0f / ((float)(cr*cc) * (float)OCAPS + EPS);
            w_s[idx] = rrv * acti_s[k];
        }
    } else {
        const float* Zown = g_z + (size_t)tile * ZPT;
        for (int idx = t; idx < ZPT; idx += 512) {
            int k = idx >> 5;
            w_s[idx] = __expf(Zown[idx] - m_s[k]) * dinv_s[k] * acti_s[k];
        }
    }
    __syncthreads();

    // ---- rrs: sum_k w[k][o], parallel ----
    {
        const int o = t & 31, seg = t >> 5;        // 16 segs x 9 k
        float sp = 0.f;
        #pragma unroll
        for (int j = 0; j < 9; j++) sp += w_s[(seg*9 + j)*OCAPS + o];
        rp[seg*OCAPS + o] = sp;
    }
    __syncthreads();
    if (t < OCAPS) {
        float s = 0.f;
        #pragma unroll
        for (int i = 0; i < 16; i++) s += rp[i*OCAPS + t];
        rrs_s[t] = s;
    }

    // ---- pass 1: weighted sums over K (k-split x vectorized) ----
    {
        const int cq = t & 3, o1 = (t >> 2) & 31, part = t >> 7;
        float4 s1 = make_float4(0.f,0.f,0.f,0.f);
        float4 s2 = make_float4(0.f,0.f,0.f,0.f);
        const int kbeg = part * 36;
        if (INIT_RR) {
            const float4* V4 = (const float4*)V;
            #pragma unroll 6
            for (int kk2 = 0; kk2 < 36; kk2++) {
                const int k = kbeg + kk2;
                float4 v = V4[k*128 + o1*4 + cq];
                float w = w_s[k*OCAPS + o1];
                s1.x = fmaf(w, v.x, s1.x); s2.x = fmaf(w*v.x, v.x, s2.x);
                s1.y = fmaf(w, v.y, s1.y); s2.y = fmaf(w*v.y, v.y, s2.y);
                s1.z = fmaf(w, v.z, s1.z); s2.z = fmaf(w*v.z, v.z, s2.z);
                s1.w = fmaf(w, v.w, s1.w); s2.w = fmaf(w*v.w, v.w, s2.w);
                union { __half2 h[2]; uint2 u; } cv;
                cv.h[0] = __floats2half2_rn(v.x, v.y);
                cv.h[1] = __floats2half2_rn(v.z, v.w);
                *(uint2*)(VH + k*512 + o1*16 + cq*4) = cv.u;
            }
        } else {
            #pragma unroll 6
            for (int kk2 = 0; kk2 < 36; kk2++) {
                const int k = kbeg + kk2;
                union { uint2 u; __half2 h[2]; } cv;
                cv.u = *(const uint2*)(VH + k*512 + o1*16 + cq*4);
                float2 f01 = __half22float2(cv.h[0]);
                float2 f23 = __half22float2(cv.h[1]);
                float w = w_s[k*OCAPS + o1];
                s1.x = fmaf(w, f01.x, s1.x); s2.x = fmaf(w*f01.x, f01.x, s2.x);
                s1.y = fmaf(w, f01.y, s1.y); s2.y = fmaf(w*f01.y, f01.y, s2.y);
                s1.z = fmaf(w, f23.x, s1.z); s2.z = fmaf(w*f23.x, f23.x, s2.z);
                s1.w = fmaf(w, f23.y, s1.w); s2.w = fmaf(w*f23.y, f23.y, s2.w);
            }
        }
        ((float4*)(ps1 + part*512))[o1*4 + cq] = s1;
        ((float4*)(ps2 + part*512))[o1*4 + cq] = s2;
    }
    __syncthreads();

    // ---- per-(o,c) stats; thread t = o*16 + c ----
    const int o = t >> 4, c = t & 15;
    const float S1 = ps1[t] + ps1[512+t] + ps1[1024+t] + ps1[1536+t];
    const float S2 = ps2[t] + ps2[512+t] + ps2[1024+t] + ps2[1536+t];

    const float rrs = rrs_s[o];
    const float inv = 1.0f / (rrs + EPS);
    const float mean = S1 * inv;
    const float var = (S2 - 2.f*mean*S1 + mean*mean*rrs) * inv;  // exact expansion

    float cj = (beta_v[o] + 0.5f*logf(var + EPS)) * rrs * LNF;
    #pragma unroll
    for (int off = 8; off > 0; off >>= 1)
        cj += __shfl_xor_sync(0xffffffffu, cj, off, 16);

    if (!FINAL) {
        float op2 = -0.5f * logf(TWO_PI * var);
        #pragma unroll
        for (int off = 8; off > 0; off >>= 1)
            op2 += __shfl_xor_sync(0xffffffffu, op2, off, 16);
        if (c == 0) op2_s[o] = op2;
        mean_cs[c*OCAPS + o] = mean;
        i2v_cs[c*OCAPS + o]  = 0.5f / var;
    }
    if (c == 0) cost_s[o] = cj;
    __syncthreads();

    if (t < OCAPS) {
        float cost = cost_s[t];
        float cm = cost;
        #pragma unroll
        for (int off = 16; off > 0; off >>= 1)
            cm += __shfl_xor_sync(0xffffffffu, cm, off);
        cm *= (1.0f/32.0f);
        float d = cost - cm;
        float ss = d*d;
        #pragma unroll
        for (int off = 16; off > 0; off >>= 1)
            ss += __shfl_xor_sync(0xffffffffu, ss, off);
        float stdv = sqrtf(ss * (1.0f/32.0f));
        float a = sigmoidf_(lam * (beta_a[t] + (cm - cost)/(stdv + EPS)));
        if (FINAL) out[204800 + tile*OCAPS + t] = a;
        else       logact_s[t] = logf(a + EPS);
    }

    if (FINAL) {
        out[(size_t)tile*512 + t] = mean;   // poses (tile, o, c)
        return;
    }
    __syncthreads();

    // ---- pass 2: z[k][o] = log(act)+op2 - sum_c (v-mean)^2/(2var) ----
    float* Z = g_z + (size_t)tile * ZPT;
    const int o2 = t & 31, k0 = t >> 5;        // warp = one k0, lanes = o
    const float zc = logact_s[o2] + op2_s[o2];
    #pragma unroll
    for (int j = 0; j < 9; j++) {
        int k = k0*9 + j;
        const uint4* vp = (const uint4*)(VH + k*512 + o2*CH);
        float s = 0.f;
        #pragma unroll
        for (int h8 = 0; h8 < 2; h8++) {
            union { uint4 u; __half2 h[4]; } cv;
            cv.u = vp[h8];
            #pragma unroll
            for (int q = 0; q < 4; q++) {
                float2 f = __half22float2(cv.h[q]);
                int cb = h8*8 + q*2;
                float d;
                d = f.x - mean_cs[(cb+0)*OCAPS + o2]; s = fmaf(d*d, i2v_cs[(cb+0)*OCAPS + o2], s);
                d = f.y - mean_cs[(cb+1)*OCAPS + o2]; s = fmaf(d*d, i2v_cs[(cb+1)*OCAPS + o2], s);
            }
        }
        Z[k*OCAPS + o2] = zc - s;
    }
}

// E-step stats: per (n, child cell, cc): softmax max + 1/denom over
// valid (parent, slot) pairs x 32 parent caps.
// grid = 4*144, 512 threads: warp = one cc (t>>5), lane = o.
__global__ void __launch_bounds__(512)
estep_kernel()
{
    const int b = blockIdx.x;
    const int n = b / NCELLS, c2 = b % NCELLS;
    const int r = c2 / 12, ccol = c2 % 12;
    const int t = threadIdx.x;
    const int cc = t >> 5, o = t & 31;

    float zb[9];
    float m = -CUDART_INF_F;
    #pragma unroll
    for (int dr = 0; dr < 3; dr++) {
        #pragma unroll
        for (int dc = 0; dc < 3; dc++) {
            const int i = dr*3 + dc;
            const int pr2 = r - dr, pc2 = ccol - dc;
            if (pr2 >= 0 && pr2 < 10 && pc2 >= 0 && pc2 < 10) {
                const int p = pr2*10 + pc2;
                const int k = i*CH + cc;
                zb[i] = g_z[((size_t)(n*100 + p))*ZPT + k*OCAPS + o];
                m = fmaxf(m, zb[i]);
            } else {
                zb[i] = -CUDART_INF_F;
            }
        }
    }
    #pragma unroll
    for (int off = 16; off > 0; off >>= 1)
        m = fmaxf(m, __shfl_xor_sync(0xffffffffu, m, off));
    if (isinf(m)) m = 0.0f;

    float s = 0.f;
    #pragma unroll
    for (int i = 0; i < 9; i++)
        s += __expf(zb[i] - m);   // exp(-inf) = 0 for invalid pairs
    #pragma unroll
    for (int off = 16; off > 0; off >>= 1)
        s += __shfl_xor_sync(0xffffffffu, s, off);

    if (o == 0) {
        const int gi = ((n*NCELLS) + c2)*CH + cc;
        g_m[gi]    = m;
        g_dinv[gi] = 1.0f / s;
    }
}

extern "C" void kernel_launch(void* const* d_in, const int* in_sizes, int n_in,
                              void* d_out, int out_size)
{
    const float* votes  = (const float*)d_in[0];
    const float* acti   = (const float*)d_in[1];
    const float* beta_v = (const float*)d_in[2];
    const float* beta_a = (const float*)d_in[3];
    float* out = (float*)d_out;

    const float lam0 = 0.01f * (1.0f - 0.95f);
    const float lam1 = 0.01f * (1.0f - 0.95f*0.95f);
    const float lam2 = 0.01f * (1.0f - 0.95f*0.95f*0.95f);

    mz_kernel<true,  false><<<NTILES, 512>>>(votes, acti, beta_v, beta_a, lam0, nullptr);
    estep_kernel<<<4*NCELLS, 512>>>();
    mz_kernel<false, false><<<NTILES, 512>>>(votes, acti, beta_v, beta_a, lam1, nullptr);
    estep_kernel<<<4*NCELLS, 512>>>();
    mz_kernel<false, true ><<<NTILES, 512>>>(votes, acti, beta_v, beta_a, lam2, out);
}

// round 10
// speedup vs baseline: 1.2714x; 1.0656x over previous
#include <cuda_runtime.h>
#include <cuda_fp16.h>
#include <math.h>
#include <math_constants.h>

// EM routing, matrix capsules.
// N=4, child 12x12, kernel 3, stride 1 -> P=10, tiles = 4*100 = 400
// K=144 (9 slots x 16 child caps), O=32 parent caps, ch=16 pose dims.
// votes: (400, 144, 32, 16) f32 ; acts: (400, 144) ; beta_v/beta_a: (32)
// Output: poses (400*32*16 = 204800 floats) then activations (400*32).
//
// R4 split structure + fp16 votes cache. R10: pass1 loads explicitly
// batched (6 x float4 register array) for MLP~6; accumulation order
// unchanged -> bitwise-identical results. launch_bounds(512,2) caps regs
// at 64 (no forced spilling; 2 CTAs/SM preserved).

#define NTILES 400
#define KTOT   144
#define OCAPS  32
#define CH     16
#define TILE_ELEMS (KTOT*OCAPS*CH)   // 73728
#define ZPT    (KTOT*OCAPS)          // 4608
#define EPS    1e-9f
#define LNF    22.2222222222222222f  // 100/(144/32)
#define TWO_PI 6.2831853071795864f
#define NCELLS 144                   // 12*12 child cells

__device__ float g_z   [NTILES*ZPT];              // (tile, k, o)
__device__ float g_m   [4*NCELLS*CH];             // softmax max per (n, cell, cc)
__device__ float g_dinv[4*NCELLS*CH];             // 1/denom per (n, cell, cc)
__device__ uint4 g_vh  [(size_t)NTILES*TILE_ELEMS/8];  // fp16 votes cache (59 MB)

__device__ __forceinline__ float sigmoidf_(float x) { return 1.0f/(1.0f+__expf(-x)); }

template<bool INIT_RR, bool FINAL>
__global__ void __launch_bounds__(512, 2)
mz_kernel(const float* __restrict__ votes, const float* __restrict__ acti,
          const float* __restrict__ beta_v, const float* __restrict__ beta_a,
          float lam, float* __restrict__ out)
{
    const int tile = blockIdx.x;
    const int n = tile / 100, p = tile % 100;
    const int pr = p / 10, pc = p % 10;
    const float* V = votes + (size_t)tile * TILE_ELEMS;
    __half* VH = ((__half*)g_vh) + (size_t)tile * TILE_ELEMS;

    __shared__ float w_s[ZPT];           // rr*act  [k][o]
    __shared__ float acti_s[KTOT];
    __shared__ float m_s[KTOT];          // softmax max per k (slot,cc)
    __shared__ float dinv_s[KTOT];
    __shared__ float ps1[4*512];         // pass1 partials [part][o*16+c]
    __shared__ float ps2[4*512];
    __shared__ float rp[16*OCAPS];       // rrs partials
    __shared__ float rrs_s[OCAPS];
    __shared__ float mean_cs[CH*OCAPS];  // [c][o]
    __shared__ float i2v_cs[CH*OCAPS];   // 1/(2 var) [c][o]
    __shared__ float cost_s[OCAPS];
    __shared__ float logact_s[OCAPS];
    __shared__ float op2_s[OCAPS];

    const int t = threadIdx.x;
    if (t < KTOT) {
        acti_s[t] = acti[tile*KTOT + t];
        if (!INIT_RR) {
            const int slot = t >> 4, ccp = t & 15;
            const int r = pr + slot/3, ccol = pc + slot%3;
            const int gi = ((n*NCELLS) + r*12 + ccol)*CH + ccp;
            m_s[t]    = g_m[gi];
            dinv_s[t] = g_dinv[gi];
        }
    }
    __syncthreads();

    // ---- build w = rr * act_i ----
    if (INIT_RR) {
        for (int idx = t; idx < ZPT; idx += 512) {
            int k = idx >> 5;
            int slot = k >> 4;
            int r = pr + slot/3, c = pc + slot%3;
            int cr = min(r,9) - max(0,r-2) + 1;
            int cc = min(c,9) - max(0,c-2) + 1;
            float rrv = 1.0f / ((float)(cr*cc) * (float)OCAPS + EPS);
            w_s[idx] = rrv * acti_s[k];
        }
    } else {
        const float* Zown = g_z + (size_t)tile * ZPT;
        for (int idx = t; idx < ZPT; idx += 512) {
            int k = idx >> 5;
            w_s[idx] = __expf(Zown[idx] - m_s[k]) * dinv_s[k] * acti_s[k];
        }
    }
    __syncthreads();

    // ---- rrs: sum_k w[k][o], parallel ----
    {
        const int o = t & 31, seg = t >> 5;        // 16 segs x 9 k
        float sp = 0.f;
        #pragma unroll
        for (int j = 0; j < 9; j++) sp += w_s[(seg*9 + j)*OCAPS + o];
        rp[seg*OCAPS + o] = sp;
    }
    __syncthreads();
    if (t < OCAPS) {
        float s = 0.f;
        #pragma unroll
        for (int i = 0; i < 16; i++) s += rp[i*OCAPS + t];
        rrs_s[t] = s;
    }

    // ---- pass 1: weighted sums over K (k-split, explicit 6-deep load batch) ----
    {
        const int cq = t & 3, o1 = (t >> 2) & 31, part = t >> 7;
        float4 s1 = make_float4(0.f,0.f,0.f,0.f);
        float4 s2 = make_float4(0.f,0.f,0.f,0.f);
        const int kbeg = part * 36;
        if (INIT_RR) {
            const float4* V4 = (const float4*)V;
            for (int kb = 0; kb < 36; kb += 6) {
                float4 vv[6];
                #pragma unroll
                for (int g = 0; g < 6; g++)
                    vv[g] = V4[(kbeg + kb + g)*128 + o1*4 + cq];
                #pragma unroll
                for (int g = 0; g < 6; g++) {
                    const int k = kbeg + kb + g;
                    const float4 v = vv[g];
                    const float w = w_s[k*OCAPS + o1];
                    s1.x = fmaf(w, v.x, s1.x); s2.x = fmaf(w*v.x, v.x, s2.x);
                    s1.y = fmaf(w, v.y, s1.y); s2.y = fmaf(w*v.y, v.y, s2.y);
                    s1.z = fmaf(w, v.z, s1.z); s2.z = fmaf(w*v.z, v.z, s2.z);
                    s1.w = fmaf(w, v.w, s1.w); s2.w = fmaf(w*v.w, v.w, s2.w);
                    union { __half2 h[2]; uint2 u; } cv;
                    cv.h[0] = __floats2half2_rn(v.x, v.y);
                    cv.h[1] = __floats2half2_rn(v.z, v.w);
                    *(uint2*)(VH + k*512 + o1*16 + cq*4) = cv.u;
                }
            }
        } else {
            for (int kb = 0; kb < 36; kb += 6) {
                uint2 hv[6];
                #pragma unroll
                for (int g = 0; g < 6; g++)
                    hv[g] = *(const uint2*)(VH + (kbeg + kb + g)*512 + o1*16 + cq*4);
                #pragma unroll
                for (int g = 0; g < 6; g++) {
                    const int k = kbeg + kb + g;
                    union { uint2 u; __half2 h[2]; } cv; cv.u = hv[g];
                    float2 f01 = __half22float2(cv.h[0]);
                    float2 f23 = __half22float2(cv.h[1]);
                    const float w = w_s[k*OCAPS + o1];
                    s1.x = fmaf(w, f01.x, s1.x); s2.x = fmaf(w*f01.x, f01.x, s2.x);
                    s1.y = fmaf(w, f01.y, s1.y); s2.y = fmaf(w*f01.y, f01.y, s2.y);
                    s1.z = fmaf(w, f23.x, s1.z); s2.z = fmaf(w*f23.x, f23.x, s2.z);
                    s1.w = fmaf(w, f23.y, s1.w); s2.w = fmaf(w*f23.y, f23.y, s2.w);
                }
            }
        }
        ((float4*)(ps1 + part*512))[o1*4 + cq] = s1;
        ((float4*)(ps2 + part*512))[o1*4 + cq] = s2;
    }
    __syncthreads();

    // ---- per-(o,c) stats; thread t = o*16 + c ----
    const int o = t >> 4, c = t & 15;
    const float S1 = ps1[t] + ps1[512+t] + ps1[1024+t] + ps1[1536+t];
    const float S2 = ps2[t] + ps2[512+t] + ps2[1024+t] + ps2[1536+t];

    const float rrs = rrs_s[o];
    const float inv = 1.0f / (rrs + EPS);
    const float mean = S1 * inv;
    const float var = (S2 - 2.f*mean*S1 + mean*mean*rrs) * inv;  // exact expansion

    float cj = (beta_v[o] + 0.5f*logf(var + EPS)) * rrs * LNF;
    #pragma unroll
    for (int off = 8; off > 0; off >>= 1)
        cj += __shfl_xor_sync(0xffffffffu, cj, off, 16);

    if (!FINAL) {
        float op2 = -0.5f * logf(TWO_PI * var);
        #pragma unroll
        for (int off = 8; off > 0; off >>= 1)
            op2 += __shfl_xor_sync(0xffffffffu, op2, off, 16);
        if (c == 0) op2_s[o] = op2;
        mean_cs[c*OCAPS + o] = mean;
        i2v_cs[c*OCAPS + o]  = 0.5f / var;
    }
    if (c == 0) cost_s[o] = cj;
    __syncthreads();

    if (t < OCAPS) {
        float cost = cost_s[t];
        float cm = cost;
        #pragma unroll
        for (int off = 16; off > 0; off >>= 1)
            cm += __shfl_xor_sync(0xffffffffu, cm, off);
        cm *= (1.0f/32.0f);
        float d = cost - cm;
        float ss = d*d;
        #pragma unroll
        for (int off = 16; off > 0; off >>= 1)
            ss += __shfl_xor_sync(0xffffffffu, ss, off);
        float stdv = sqrtf(ss * (1.0f/32.0f));
        float a = sigmoidf_(lam * (beta_a[t] + (cm - cost)/(stdv + EPS)));
        if (FINAL) out[204800 + tile*OCAPS + t] = a;
        else       logact_s[t] = logf(a + EPS);
    }

    if (FINAL) {
        out[(size_t)tile*512 + t] = mean;   // poses (tile, o, c)
        return;
    }
    __syncthreads();

    // ---- pass 2: z[k][o] = log(act)+op2 - sum_c (v-mean)^2/(2var) ----
    float* Z = g_z + (size_t)tile * ZPT;
    const int o2 = t & 31, k0 = t >> 5;        // warp = one k0, lanes = o
    const float zc = logact_s[o2] + op2_s[o2];
    #pragma unroll
    for (int j = 0; j < 9; j++) {
        int k = k0*9 + j;
        const uint4* vp = (const uint4*)(VH + k*512 + o2*CH);
        float s = 0.f;
        #pragma unroll
        for (int h8 = 0; h8 < 2; h8++) {
            union { uint4 u; __half2 h[4]; } cv;
            cv.u = vp[h8];
            #pragma unroll
            for (int q = 0; q < 4; q++) {
                float2 f = __half22float2(cv.h[q]);
                int cb = h8*8 + q*2;
                float d;
                d = f.x - mean_cs[(cb+0)*OCAPS + o2]; s = fmaf(d*d, i2v_cs[(cb+0)*OCAPS + o2], s);
                d = f.y - mean_cs[(cb+1)*OCAPS + o2]; s = fmaf(d*d, i2v_cs[(cb+1)*OCAPS + o2], s);
            }
        }
        Z[k*OCAPS + o2] = zc - s;
    }
}

// E-step stats: per (n, child cell, cc): softmax max + 1/denom over
// valid (parent, slot) pairs x 32 parent caps.
// grid = 4*144, 512 threads: warp = one cc (t>>5), lane = o.
__global__ void __launch_bounds__(512)
estep_kernel()
{
    const int b = blockIdx.x;
    const int n = b / NCELLS, c2 = b % NCELLS;
    const int r = c2 / 12, ccol = c2 % 12;
    const int t = threadIdx.x;
    const int cc = t >> 5, o = t & 31;

    float zb[9];
    float m = -CUDART_INF_F;
    #pragma unroll
    for (int dr = 0; dr < 3; dr++) {
        #pragma unroll
        for (int dc = 0; dc < 3; dc++) {
            const int i = dr*3 + dc;
            const int pr2 = r - dr, pc2 = ccol - dc;
            if (pr2 >= 0 && pr2 < 10 && pc2 >= 0 && pc2 < 10) {
                const int p = pr2*10 + pc2;
                const int k = i*CH + cc;
                zb[i] = g_z[((size_t)(n*100 + p))*ZPT + k*OCAPS + o];
                m = fmaxf(m, zb[i]);
            } else {
                zb[i] = -CUDART_INF_F;
            }
        }
    }
    #pragma unroll
    for (int off = 16; off > 0; off >>= 1)
        m = fmaxf(m, __shfl_xor_sync(0xffffffffu, m, off));
    if (isinf(m)) m = 0.0f;

    float s = 0.f;
    #pragma unroll
    for (int i = 0; i < 9; i++)
        s += __expf(zb[i] - m);   // exp(-inf) = 0 for invalid pairs
    #pragma unroll
    for (int off = 16; off > 0; off >>= 1)
        s += __shfl_xor_sync(0xffffffffu, s, off);

    if (o == 0) {
        const int gi = ((n*NCELLS) + c2)*CH + cc;
        g_m[gi]    = m;
        g_dinv[gi] = 1.0f / s;
    }
}

extern "C" void kernel_launch(void* const* d_in, const int* in_sizes, int n_in,
                              void* d_out, int out_size)
{
    const float* votes  = (const float*)d_in[0];
    const float* acti   = (const float*)d_in[1];
    const float* beta_v = (const float*)d_in[2];
    const float* beta_a = (const float*)d_in[3];
    float* out = (float*)d_out;

    const float lam0 = 0.01f * (1.0f - 0.95f);
    const float lam1 = 0.01f * (1.0f - 0.95f*0.95f);
    const float lam2 = 0.01f * (1.0f - 0.95f*0.95f*0.95f);

    mz_kernel<true,  false><<<NTILES, 512>>>(votes, acti, beta_v, beta_a, lam0, nullptr);
    estep_kernel<<<4*NCELLS, 512>>>();
    mz_kernel<false, false><<<NTILES, 512>>>(votes, acti, beta_v, beta_a, lam1, nullptr);
    estep_kernel<<<4*NCELLS, 512>>>();
    mz_kernel<false, true ><<<NTILES, 512>>>(votes, acti, beta_v, beta_a, lam2, out);
}

// round 11
// speedup vs baseline: 1.3270x; 1.0438x over previous
#include <cuda_runtime.h>
#include <cuda_fp16.h>
#include <math.h>
#include <math_constants.h>

// EM routing, matrix capsules.
// N=4, child 12x12, kernel 3, stride 1 -> P=10, tiles = 4*100 = 400
// K=144 (9 slots x 16 child caps), O=32 parent caps, ch=16 pose dims.
// votes: (400, 144, 32, 16) f32 ; acts: (400, 144) ; beta_v/beta_a: (32)
// Output: poses (400*32*16 = 204800 floats) then activations (400*32).
//
// R11: 256-thread CTAs (each thread covers 2 old slots in sequential
// rounds -> bitwise-identical arithmetic). 400 CTAs now ALL resident in
// one wave (was 1.35 waves at 512 threads / 2 CTAs/SM), removing the
// wave-quantization tail that held mz0 at 45% DRAM.

#define NTILES 400
#define KTOT   144
#define OCAPS  32
#define CH     16
#define TILE_ELEMS (KTOT*OCAPS*CH)   // 73728
#define ZPT    (KTOT*OCAPS)          // 4608
#define EPS    1e-9f
#define LNF    22.2222222222222222f  // 100/(144/32)
#define TWO_PI 6.2831853071795864f
#define NCELLS 144                   // 12*12 child cells
#define NT     256

__device__ float g_z   [NTILES*ZPT];              // (tile, k, o)
__device__ float g_m   [4*NCELLS*CH];             // softmax max per (n, cell, cc)
__device__ float g_dinv[4*NCELLS*CH];             // 1/denom per (n, cell, cc)
__device__ uint4 g_vh  [(size_t)NTILES*TILE_ELEMS/8];  // fp16 votes cache (59 MB)

__device__ __forceinline__ float sigmoidf_(float x) { return 1.0f/(1.0f+__expf(-x)); }

template<bool INIT_RR, bool FINAL>
__global__ void __launch_bounds__(NT)
mz_kernel(const float* __restrict__ votes, const float* __restrict__ acti,
          const float* __restrict__ beta_v, const float* __restrict__ beta_a,
          float lam, float* __restrict__ out)
{
    const int tile = blockIdx.x;
    const int n = tile / 100, p = tile % 100;
    const int pr = p / 10, pc = p % 10;
    const float* V = votes + (size_t)tile * TILE_ELEMS;
    __half* VH = ((__half*)g_vh) + (size_t)tile * TILE_ELEMS;

    __shared__ float w_s[ZPT];           // rr*act  [k][o]
    __shared__ float acti_s[KTOT];
    __shared__ float m_s[KTOT];          // softmax max per k (slot,cc)
    __shared__ float dinv_s[KTOT];
    __shared__ float ps1[4*512];         // pass1 partials [part][o*16+c]
    __shared__ float ps2[4*512];
    __shared__ float rp[16*OCAPS];       // rrs partials
    __shared__ float rrs_s[OCAPS];
    __shared__ float mean_cs[CH*OCAPS];  // [c][o]
    __shared__ float i2v_cs[CH*OCAPS];   // 1/(2 var) [c][o]
    __shared__ float cost_s[OCAPS];
    __shared__ float logact_s[OCAPS];
    __shared__ float op2_s[OCAPS];

    const int t = threadIdx.x;
    if (t < KTOT) {
        acti_s[t] = acti[tile*KTOT + t];
        if (!INIT_RR) {
            const int slot = t >> 4, ccp = t & 15;
            const int r = pr + slot/3, ccol = pc + slot%3;
            const int gi = ((n*NCELLS) + r*12 + ccol)*CH + ccp;
            m_s[t]    = g_m[gi];
            dinv_s[t] = g_dinv[gi];
        }
    }
    __syncthreads();

    // ---- build w = rr * act_i (elementwise; stride change is exact) ----
    if (INIT_RR) {
        for (int idx = t; idx < ZPT; idx += NT) {
            int k = idx >> 5;
            int slot = k >> 4;
            int r = pr + slot/3, c = pc + slot%3;
            int cr = min(r,9) - max(0,r-2) + 1;
            int cc = min(c,9) - max(0,c-2) + 1;
            float rrv = 1.0f / ((float)(cr*cc) * (float)OCAPS + EPS);
            w_s[idx] = rrv * acti_s[k];
        }
    } else {
        const float* Zown = g_z + (size_t)tile * ZPT;
        for (int idx = t; idx < ZPT; idx += NT) {
            int k = idx >> 5;
            w_s[idx] = __expf(Zown[idx] - m_s[k]) * dinv_s[k] * acti_s[k];
        }
    }
    __syncthreads();

    // ---- rrs partials: 8 warps x 2 rounds cover 16 segs (per-seg sums exact) ----
    {
        const int o = t & 31, w = t >> 5;          // w in 0..7
        #pragma unroll
        for (int round = 0; round < 2; round++) {
            const int seg = w + 8*round;
            float sp = 0.f;
            #pragma unroll
            for (int j = 0; j < 9; j++) sp += w_s[(seg*9 + j)*OCAPS + o];
            rp[seg*OCAPS + o] = sp;
        }
    }
    __syncthreads();
    if (t < OCAPS) {
        float s = 0.f;
        #pragma unroll
        for (int i = 0; i < 16; i++) s += rp[i*OCAPS + t];
        rrs_s[t] = s;
    }

    // ---- pass 1: 2 rounds, each = one old (part,o,cq) slot; chains exact ----
    {
        #pragma unroll
        for (int round = 0; round < 2; round++) {
            const int slot = t + NT*round;          // 0..511
            const int cq = slot & 3, o1 = (slot >> 2) & 31, part = slot >> 7;
            float4 s1 = make_float4(0.f,0.f,0.f,0.f);
            float4 s2 = make_float4(0.f,0.f,0.f,0.f);
            const int kbeg = part * 36;
            if (INIT_RR) {
                const float4* V4 = (const float4*)V;
                for (int kb = 0; kb < 36; kb += 6) {
                    float4 vv[6];
                    #pragma unroll
                    for (int g = 0; g < 6; g++)
                        vv[g] = V4[(kbeg + kb + g)*128 + o1*4 + cq];
                    #pragma unroll
                    for (int g = 0; g < 6; g++) {
                        const int k = kbeg + kb + g;
                        const float4 v = vv[g];
                        const float w = w_s[k*OCAPS + o1];
                        s1.x = fmaf(w, v.x, s1.x); s2.x = fmaf(w*v.x, v.x, s2.x);
                        s1.y = fmaf(w, v.y, s1.y); s2.y = fmaf(w*v.y, v.y, s2.y);
                        s1.z = fmaf(w, v.z, s1.z); s2.z = fmaf(w*v.z, v.z, s2.z);
                        s1.w = fmaf(w, v.w, s1.w); s2.w = fmaf(w*v.w, v.w, s2.w);
                        union { __half2 h[2]; uint2 u; } cv;
                        cv.h[0] = __floats2half2_rn(v.x, v.y);
                        cv.h[1] = __floats2half2_rn(v.z, v.w);
                        *(uint2*)(VH + k*512 + o1*16 + cq*4) = cv.u;
                    }
                }
            } else {
                for (int kb = 0; kb < 36; kb += 6) {
                    uint2 hv[6];
                    #pragma unroll
                    for (int g = 0; g < 6; g++)
                        hv[g] = *(const uint2*)(VH + (kbeg + kb + g)*512 + o1*16 + cq*4);
                    #pragma unroll
                    for (int g = 0; g < 6; g++) {
                        const int k = kbeg + kb + g;
                        union { uint2 u; __half2 h[2]; } cv; cv.u = hv[g];
                        float2 f01 = __half22float2(cv.h[0]);
                        float2 f23 = __half22float2(cv.h[1]);
                        const float w = w_s[k*OCAPS + o1];
                        s1.x = fmaf(w, f01.x, s1.x); s2.x = fmaf(w*f01.x, f01.x, s2.x);
                        s1.y = fmaf(w, f01.y, s1.y); s2.y = fmaf(w*f01.y, f01.y, s2.y);
                        s1.z = fmaf(w, f23.x, s1.z); s2.z = fmaf(w*f23.x, f23.x, s2.z);
                        s1.w = fmaf(w, f23.y, s1.w); s2.w = fmaf(w*f23.y, f23.y, s2.w);
                    }
                }
            }
            ((float4*)(ps1 + part*512))[o1*4 + cq] = s1;
            ((float4*)(ps2 + part*512))[o1*4 + cq] = s2;
        }
    }
    __syncthreads();

    // ---- per-(o,c) stats: 2 rounds over old slot space; shuffles exact ----
    #pragma unroll
    for (int round = 0; round < 2; round++) {
        const int slot = t + NT*round;
        const int o = slot >> 4, c = slot & 15;
        const float S1 = ps1[slot] + ps1[512+slot] + ps1[1024+slot] + ps1[1536+slot];
        const float S2 = ps2[slot] + ps2[512+slot] + ps2[1024+slot] + ps2[1536+slot];

        const float rrs = rrs_s[o];
        const float inv = 1.0f / (rrs + EPS);
        const float mean = S1 * inv;
        const float var = (S2 - 2.f*mean*S1 + mean*mean*rrs) * inv;  // exact expansion

        float cj = (beta_v[o] + 0.5f*logf(var + EPS)) * rrs * LNF;
        #pragma unroll
        for (int off = 8; off > 0; off >>= 1)
            cj += __shfl_xor_sync(0xffffffffu, cj, off, 16);

        if (!FINAL) {
            float op2 = -0.5f * logf(TWO_PI * var);
            #pragma unroll
            for (int off = 8; off > 0; off >>= 1)
                op2 += __shfl_xor_sync(0xffffffffu, op2, off, 16);
            if (c == 0) op2_s[o] = op2;
            mean_cs[c*OCAPS + o] = mean;
            i2v_cs[c*OCAPS + o]  = 0.5f / var;
        }
        if (c == 0) cost_s[o] = cj;
        if (FINAL) out[(size_t)tile*512 + slot] = mean;   // poses (tile, o, c)
    }
    __syncthreads();

    if (t < OCAPS) {
        float cost = cost_s[t];
        float cm = cost;
        #pragma unroll
        for (int off = 16; off > 0; off >>= 1)
            cm += __shfl_xor_sync(0xffffffffu, cm, off);
        cm *= (1.0f/32.0f);
        float d = cost - cm;
        float ss = d*d;
        #pragma unroll
        for (int off = 16; off > 0; off >>= 1)
            ss += __shfl_xor_sync(0xffffffffu, ss, off);
        float stdv = sqrtf(ss * (1.0f/32.0f));
        float a = sigmoidf_(lam * (beta_a[t] + (cm - cost)/(stdv + EPS)));
        if (FINAL) out[204800 + tile*OCAPS + t] = a;
        else       logact_s[t] = logf(a + EPS);
    }

    if (FINAL) return;
    __syncthreads();

    // ---- pass 2: 8 warps x 2 rounds cover k0 = 0..15; per-k rows exact ----
    float* Z = g_z + (size_t)tile * ZPT;
    const int o2 = t & 31, w8 = t >> 5;        // w8 in 0..7
    const float zc = logact_s[o2] + op2_s[o2];
    #pragma unroll
    for (int round = 0; round < 2; round++) {
        const int k0 = w8 + 8*round;
        #pragma unroll
        for (int j = 0; j < 9; j++) {
            int k = k0*9 + j;
            const uint4* vp = (const uint4*)(VH + k*512 + o2*CH);
            float s = 0.f;
            #pragma unroll
            for (int h8 = 0; h8 < 2; h8++) {
                union { uint4 u; __half2 h[4]; } cv;
                cv.u = vp[h8];
                #pragma unroll
                for (int q = 0; q < 4; q++) {
                    float2 f = __half22float2(cv.h[q]);
                    int cb = h8*8 + q*2;
                    float d;
                    d = f.x - mean_cs[(cb+0)*OCAPS + o2]; s = fmaf(d*d, i2v_cs[(cb+0)*OCAPS + o2], s);
                    d = f.y - mean_cs[(cb+1)*OCAPS + o2]; s = fmaf(d*d, i2v_cs[(cb+1)*OCAPS + o2], s);
                }
            }
            Z[k*OCAPS + o2] = zc - s;
        }
    }
}

// E-step stats: per (n, child cell, cc): softmax max + 1/denom over
// valid (parent, slot) pairs x 32 parent caps.
// grid = 4*144, 512 threads: warp = one cc (t>>5), lane = o.
__global__ void __launch_bounds__(512)
estep_kernel()
{
    const int b = blockIdx.x;
    const int n = b / NCELLS, c2 = b % NCELLS;
    const int r = c2 / 12, ccol = c2 % 12;
    const int t = threadIdx.x;
    const int cc = t >> 5, o = t & 31;

    float zb[9];
    float m = -CUDART_INF_F;
    #pragma unroll
    for (int dr = 0; dr < 3; dr++) {
        #pragma unroll
        for (int dc = 0; dc < 3; dc++) {
            const int i = dr*3 + dc;
            const int pr2 = r - dr, pc2 = ccol - dc;
            if (pr2 >= 0 && pr2 < 10 && pc2 >= 0 && pc2 < 10) {
                const int p = pr2*10 + pc2;
                const int k = i*CH + cc;
                zb[i] = g_z[((size_t)(n*100 + p))*ZPT + k*OCAPS + o];
                m = fmaxf(m, zb[i]);
            } else {
                zb[i] = -CUDART_INF_F;
            }
        }
    }
    #pragma unroll
    for (int off = 16; off > 0; off >>= 1)
        m = fmaxf(m, __shfl_xor_sync(0xffffffffu, m, off));
    if (isinf(m)) m = 0.0f;

    float s = 0.f;
    #pragma unroll
    for (int i = 0; i < 9; i++)
        s += __expf(zb[i] - m);   // exp(-inf) = 0 for invalid pairs
    #pragma unroll
    for (int off = 16; off > 0; off >>= 1)
        s += __shfl_xor_sync(0xffffffffu, s, off);

    if (o == 0) {
        const int gi = ((n*NCELLS) + c2)*CH + cc;
        g_m[gi]    = m;
        g_dinv[gi] = 1.0f / s;
    }
}

extern "C" void kernel_launch(void* const* d_in, const int* in_sizes, int n_in,
                              void* d_out, int out_size)
{
    const float* votes  = (const float*)d_in[0];
    const float* acti   = (const float*)d_in[1];
    const float* beta_v = (const float*)d_in[2];
    const float* beta_a = (const float*)d_in[3];
    float* out = (float*)d_out;

    const float lam0 = 0.01f * (1.0f - 0.95f);
    const float lam1 = 0.01f * (1.0f - 0.95f*0.95f);
    const float lam2 = 0.01f * (1.0f - 0.95f*0.95f*0.95f);

    mz_kernel<true,  false><<<NTILES, NT>>>(votes, acti, beta_v, beta_a, lam0, nullptr);
    estep_kernel<<<4*NCELLS, 512>>>();
    mz_kernel<false, false><<<NTILES, NT>>>(votes, acti, beta_v, beta_a, lam1, nullptr);
    estep_kernel<<<4*NCELLS, 512>>>();
    mz_kernel<false, true ><<<NTILES, NT>>>(votes, acti, beta_v, beta_a, lam2, out);
}

// round 13
// speedup vs baseline: 1.4652x; 1.1041x over previous
#include <cuda_runtime.h>
#include <cuda_fp16.h>
#include <math.h>
#include <math_constants.h>

// EM routing, matrix capsules.
// N=4, child 12x12, kernel 3, stride 1 -> P=10, tiles = 4*100 = 400
// K=144 (9 slots x 16 child caps), O=32 parent caps, ch=16 pose dims.
// votes: (400, 144, 32, 16) f32 ; acts: (400, 144) ; beta_v/beta_a: (32)
// Output: poses (400*32*16 = 204800 floats) then activations (400*32).
//
// R11 structure (256-thread CTAs, single wave, fp16 votes cache, split
// estep). R12: fp32 votes are loaded with __ldcs (evict-first) in mz0 --
// they are single-use, so they must not evict the 59 MB fp16 cache + z
// from L2 that mz1/mz2 depend on.

#define NTILES 400
#define KTOT   144
#define OCAPS  32
#define CH     16
#define TILE_ELEMS (KTOT*OCAPS*CH)   // 73728
#define ZPT    (KTOT*OCAPS)          // 4608
#define EPS    1e-9f
#define LNF    22.2222222222222222f  // 100/(144/32)
#define TWO_PI 6.2831853071795864f
#define NCELLS 144                   // 12*12 child cells
#define NT     256

__device__ float g_z   [NTILES*ZPT];              // (tile, k, o)
__device__ float g_m   [4*NCELLS*CH];             // softmax max per (n, cell, cc)
__device__ float g_dinv[4*NCELLS*CH];             // 1/denom per (n, cell, cc)
__device__ uint4 g_vh  [(size_t)NTILES*TILE_ELEMS/8];  // fp16 votes cache (59 MB)

__device__ __forceinline__ float sigmoidf_(float x) { return 1.0f/(1.0f+__expf(-x)); }

template<bool INIT_RR, bool FINAL>
__global__ void __launch_bounds__(NT)
mz_kernel(const float* __restrict__ votes, const float* __restrict__ acti,
          const float* __restrict__ beta_v, const float* __restrict__ beta_a,
          float lam, float* __restrict__ out)
{
    const int tile = blockIdx.x;
    const int n = tile / 100, p = tile % 100;
    const int pr = p / 10, pc = p % 10;
    const float* V = votes + (size_t)tile * TILE_ELEMS;
    __half* VH = ((__half*)g_vh) + (size_t)tile * TILE_ELEMS;

    __shared__ float w_s[ZPT];           // rr*act  [k][o]
    __shared__ float acti_s[KTOT];
    __shared__ float m_s[KTOT];          // softmax max per k (slot,cc)
    __shared__ float dinv_s[KTOT];
    __shared__ float ps1[4*512];         // pass1 partials [part][o*16+c]
    __shared__ float ps2[4*512];
    __shared__ float rp[16*OCAPS];       // rrs partials
    __shared__ float rrs_s[OCAPS];
    __shared__ float mean_cs[CH*OCAPS];  // [c][o]
    __shared__ float i2v_cs[CH*OCAPS];   // 1/(2 var) [c][o]
    __shared__ float cost_s[OCAPS];
    __shared__ float logact_s[OCAPS];
    __shared__ float op2_s[OCAPS];

    const int t = threadIdx.x;
    if (t < KTOT) {
        acti_s[t] = acti[tile*KTOT + t];
        if (!INIT_RR) {
            const int slot = t >> 4, ccp = t & 15;
            const int r = pr + slot/3, ccol = pc + slot%3;
            const int gi = ((n*NCELLS) + r*12 + ccol)*CH + ccp;
            m_s[t]    = g_m[gi];
            dinv_s[t] = g_dinv[gi];
        }
    }
    __syncthreads();

    // ---- build w = rr * act_i ----
    if (INIT_RR) {
        for (int idx = t; idx < ZPT; idx += NT) {
            int k = idx >> 5;
            int slot = k >> 4;
            int r = pr + slot/3, c = pc + slot%3;
            int cr = min(r,9) - max(0,r-2) + 1;
            int cc = min(c,9) - max(0,c-2) + 1;
            float rrv = 1.0f / ((float)(cr*cc) * (float)OCAPS + EPS);
            w_s[idx] = rrv * acti_s[k];
        }
    } else {
        const float* Zown = g_z + (size_t)tile * ZPT;
        for (int idx = t; idx < ZPT; idx += NT) {
            int k = idx >> 5;
            w_s[idx] = __expf(Zown[idx] - m_s[k]) * dinv_s[k] * acti_s[k];
        }
    }
    __syncthreads();

    // ---- rrs partials: 8 warps x 2 rounds cover 16 segs ----
    {
        const int o = t & 31, w = t >> 5;          // w in 0..7
        #pragma unroll
        for (int round = 0; round < 2; round++) {
            const int seg = w + 8*round;
            float sp = 0.f;
            #pragma unroll
            for (int j = 0; j < 9; j++) sp += w_s[(seg*9 + j)*OCAPS + o];
            rp[seg*OCAPS + o] = sp;
        }
    }
    __syncthreads();
    if (t < OCAPS) {
        float s = 0.f;
        #pragma unroll
        for (int i = 0; i < 16; i++) s += rp[i*OCAPS + t];
        rrs_s[t] = s;
    }

    // ---- pass 1: 2 rounds, each = one old (part,o,cq) slot ----
    {
        #pragma unroll
        for (int round = 0; round < 2; round++) {
            const int slot = t + NT*round;          // 0..511
            const int cq = slot & 3, o1 = (slot >> 2) & 31, part = slot >> 7;
            float4 s1 = make_float4(0.f,0.f,0.f,0.f);
            float4 s2 = make_float4(0.f,0.f,0.f,0.f);
            const int kbeg = part * 36;
            if (INIT_RR) {
                const float4* V4 = (const float4*)V;
                for (int kb = 0; kb < 36; kb += 6) {
                    float4 vv[6];
                    #pragma unroll
                    for (int g = 0; g < 6; g++)
                        vv[g] = __ldcs(&V4[(kbeg + kb + g)*128 + o1*4 + cq]);  // evict-first: single-use stream
                    #pragma unroll
                    for (int g = 0; g < 6; g++) {
                        const int k = kbeg + kb + g;
                        const float4 v = vv[g];
                        const float w = w_s[k*OCAPS + o1];
                        s1.x = fmaf(w, v.x, s1.x); s2.x = fmaf(w*v.x, v.x, s2.x);
                        s1.y = fmaf(w, v.y, s1.y); s2.y = fmaf(w*v.y, v.y, s2.y);
                        s1.z = fmaf(w, v.z, s1.z); s2.z = fmaf(w*v.z, v.z, s2.z);
                        s1.w = fmaf(w, v.w, s1.w); s2.w = fmaf(w*v.w, v.w, s2.w);
                        union { __half2 h[2]; uint2 u; } cv;
                        cv.h[0] = __floats2half2_rn(v.x, v.y);
                        cv.h[1] = __floats2half2_rn(v.z, v.w);
                        *(uint2*)(VH + k*512 + o1*16 + cq*4) = cv.u;
                    }
                }
            } else {
                for (int kb = 0; kb < 36; kb += 6) {
                    uint2 hv[6];
                    #pragma unroll
                    for (int g = 0; g < 6; g++)
                        hv[g] = *(const uint2*)(VH + (kbeg + kb + g)*512 + o1*16 + cq*4);
                    #pragma unroll
                    for (int g = 0; g < 6; g++) {
                        const int k = kbeg + kb + g;
                        union { uint2 u; __half2 h[2]; } cv; cv.u = hv[g];
                        float2 f01 = __half22float2(cv.h[0]);
                        float2 f23 = __half22float2(cv.h[1]);
                        const float w = w_s[k*OCAPS + o1];
                        s1.x = fmaf(w, f01.x, s1.x); s2.x = fmaf(w*f01.x, f01.x, s2.x);
                        s1.y = fmaf(w, f01.y, s1.y); s2.y = fmaf(w*f01.y, f01.y, s2.y);
                        s1.z = fmaf(w, f23.x, s1.z); s2.z = fmaf(w*f23.x, f23.x, s2.z);
                        s1.w = fmaf(w, f23.y, s1.w); s2.w = fmaf(w*f23.y, f23.y, s2.w);
                    }
                }
            }
            ((float4*)(ps1 + part*512))[o1*4 + cq] = s1;
            ((float4*)(ps2 + part*512))[o1*4 + cq] = s2;
        }
    }
    __syncthreads();

    // ---- per-(o,c) stats: 2 rounds over old slot space ----
    #pragma unroll
    for (int round = 0; round < 2; round++) {
        const int slot = t + NT*round;
        const int o = slot >> 4, c = slot & 15;
        const float S1 = ps1[slot] + ps1[512+slot] + ps1[1024+slot] + ps1[1536+slot];
        const float S2 = ps2[slot] + ps2[512+slot] + ps2[1024+slot] + ps2[1536+slot];

        const float rrs = rrs_s[o];
        const float inv = 1.0f / (rrs + EPS);
        const float mean = S1 * inv;
        const float var = (S2 - 2.f*mean*S1 + mean*mean*rrs) * inv;  // exact expansion

        float cj = (beta_v[o] + 0.5f*logf(var + EPS)) * rrs * LNF;
        #pragma unroll
        for (int off = 8; off > 0; off >>= 1)
            cj += __shfl_xor_sync(0xffffffffu, cj, off, 16);

        if (!FINAL) {
            float op2 = -0.5f * logf(TWO_PI * var);
            #pragma unroll
            for (int off = 8; off > 0; off >>= 1)
                op2 += __shfl_xor_sync(0xffffffffu, op2, off, 16);
            if (c == 0) op2_s[o] = op2;
            mean_cs[c*OCAPS + o] = mean;
            i2v_cs[c*OCAPS + o]  = 0.5f / var;
        }
        if (c == 0) cost_s[o] = cj;
        if (FINAL) out[(size_t)tile*512 + slot] = mean;   // poses (tile, o, c)
    }
    __syncthreads();

    if (t < OCAPS) {
        float cost = cost_s[t];
        float cm = cost;
        #pragma unroll
        for (int off = 16; off > 0; off >>= 1)
            cm += __shfl_xor_sync(0xffffffffu, cm, off);
        cm *= (1.0f/32.0f);
        float d = cost - cm;
        float ss = d*d;
        #pragma unroll
        for (int off = 16; off > 0; off >>= 1)
            ss += __shfl_xor_sync(0xffffffffu, ss, off);
        float stdv = sqrtf(ss * (1.0f/32.0f));
        float a = sigmoidf_(lam * (beta_a[t] + (cm - cost)/(stdv + EPS)));
        if (FINAL) out[204800 + tile*OCAPS + t] = a;
        else       logact_s[t] = logf(a + EPS);
    }

    if (FINAL) return;
    __syncthreads();

    // ---- pass 2: 8 warps x 2 rounds cover k0 = 0..15 ----
    float* Z = g_z + (size_t)tile * ZPT;
    const int o2 = t & 31, w8 = t >> 5;        // w8 in 0..7
    const float zc = logact_s[o2] + op2_s[o2];
    #pragma unroll
    for (int round = 0; round < 2; round++) {
        const int k0 = w8 + 8*round;
        #pragma unroll
        for (int j = 0; j < 9; j++) {
            int k = k0*9 + j;
            const uint4* vp = (const uint4*)(VH + k*512 + o2*CH);
            float s = 0.f;
            #pragma unroll
            for (int h8 = 0; h8 < 2; h8++) {
                union { uint4 u; __half2 h[4]; } cv;
                cv.u = vp[h8];
                #pragma unroll
                for (int q = 0; q < 4; q++) {
                    float2 f = __half22float2(cv.h[q]);
                    int cb = h8*8 + q*2;
                    float d;
                    d = f.x - mean_cs[(cb+0)*OCAPS + o2]; s = fmaf(d*d, i2v_cs[(cb+0)*OCAPS + o2], s);
                    d = f.y - mean_cs[(cb+1)*OCAPS + o2]; s = fmaf(d*d, i2v_cs[(cb+1)*OCAPS + o2], s);
                }
            }
            Z[k*OCAPS + o2] = zc - s;
        }
    }
}

// E-step stats: per (n, child cell, cc): softmax max + 1/denom over
// valid (parent, slot) pairs x 32 parent caps.
// grid = 4*144, 512 threads: warp = one cc (t>>5), lane = o.
__global__ void __launch_bounds__(512)
estep_kernel()
{
    const int b = blockIdx.x;
    const int n = b / NCELLS, c2 = b % NCELLS;
    const int r = c2 / 12, ccol = c2 % 12;
    const int t = threadIdx.x;
    const int cc = t >> 5, o = t & 31;

    float zb[9];
    float m = -CUDART_INF_F;
    #pragma unroll
    for (int dr = 0; dr < 3; dr++) {
        #pragma unroll
        for (int dc = 0; dc < 3; dc++) {
            const int i = dr*3 + dc;
            const int pr2 = r - dr, pc2 = ccol - dc;
            if (pr2 >= 0 && pr2 < 10 && pc2 >= 0 && pc2 < 10) {
                const int p = pr2*10 + pc2;
                const int k = i*CH + cc;
                zb[i] = g_z[((size_t)(n*100 + p))*ZPT + k*OCAPS + o];
                m = fmaxf(m, zb[i]);
            } else {
                zb[i] = -CUDART_INF_F;
            }
        }
    }
    #pragma unroll
    for (int off = 16; off > 0; off >>= 1)
        m = fmaxf(m, __shfl_xor_sync(0xffffffffu, m, off));
    if (isinf(m)) m = 0.0f;

    float s = 0.f;
    #pragma unroll
    for (int i = 0; i < 9; i++)
        s += __expf(zb[i] - m);   // exp(-inf) = 0 for invalid pairs
    #pragma unroll
    for (int off = 16; off > 0; off >>= 1)
        s += __shfl_xor_sync(0xffffffffu, s, off);

    if (o == 0) {
        const int gi = ((n*NCELLS) + c2)*CH + cc;
        g_m[gi]    = m;
        g_dinv[gi] = 1.0f / s;
    }
}

extern "C" void kernel_launch(void* const* d_in, const int* in_sizes, int n_in,
                              void* d_out, int out_size)
{
    const float* votes  = (const float*)d_in[0];
    const float* acti   = (const float*)d_in[1];
    const float* beta_v = (const float*)d_in[2];
    const float* beta_a = (const float*)d_in[3];
    float* out = (float*)d_out;

    const float lam0 = 0.01f * (1.0f - 0.95f);
    const float lam1 = 0.01f * (1.0f - 0.95f*0.95f);
    const float lam2 = 0.01f * (1.0f - 0.95f*0.95f*0.95f);

    mz_kernel<true,  false><<<NTILES, NT>>>(votes, acti, beta_v, beta_a, lam0, nullptr);
    estep_kernel<<<4*NCELLS, 512>>>();
    mz_kernel<false, false><<<NTILES, NT>>>(votes, acti, beta_v, beta_a, lam1, nullptr);
    estep_kernel<<<4*NCELLS, 512>>>();
    mz_kernel<false, true ><<<NTILES, NT>>>(votes, acti, beta_v, beta_a, lam2, out);
}